// round 16
// baseline (speedup 1.0000x reference)
#include <cuda_runtime.h>
#include <cuda_fp16.h>
#include <cstdint>

#define EPS 1e-5f
#define HW 784
#define NTOT 50176

// ============================ device scratch ================================
__device__ __align__(1024) __half g_x[(size_t)NTOT * 1024];  // X:  [n][1024]
__device__ __align__(1024) __half g_o1[(size_t)NTOT * 256];  // o1: [n][256]
__device__ __align__(1024) __half g_o2[(size_t)NTOT * 256];  // o2: [n][256]
__device__ __align__(1024) __half g_w1[256 * 1024];          // [co][1024]
__device__ __align__(1024) __half g_w2[256 * 2304];          // [co][2304], k=tap*256+ci
__device__ __align__(1024) __half g_w3[1024 * 256];          // [co][256]

// ============================ PTX helpers ===================================
__device__ __forceinline__ uint32_t smem_u32(const void* p) {
    uint32_t a;
    asm("{ .reg .u64 t; cvta.to.shared.u64 t, %1; cvt.u32.u64 %0, t; }" : "=r"(a) : "l"(p));
    return a;
}
__device__ __forceinline__ void cp16(uint32_t s, const void* g, uint32_t sz) {
    asm volatile("cp.async.cg.shared.global [%0], [%1], 16, %2;"
                 :: "r"(s), "l"(g), "r"(sz));
}
#define CP_COMMIT() asm volatile("cp.async.commit_group;" ::: "memory")
#define CP_WAIT(N)  asm volatile("cp.async.wait_group %0;" :: "n"(N) : "memory")

__device__ __forceinline__ void ldm4(uint32_t a, uint32_t r[4]) {
    asm volatile("ldmatrix.sync.aligned.m8n8.x4.shared.b16 {%0,%1,%2,%3}, [%4];"
                 : "=r"(r[0]), "=r"(r[1]), "=r"(r[2]), "=r"(r[3]) : "r"(a));
}
__device__ __forceinline__ void ldm2(uint32_t a, uint32_t r[2]) {
    asm volatile("ldmatrix.sync.aligned.m8n8.x2.shared.b16 {%0,%1}, [%2];"
                 : "=r"(r[0]), "=r"(r[1]) : "r"(a));
}
__device__ __forceinline__ void mma16816(float d[4], const uint32_t a[4], const uint32_t b[2]) {
    asm("mma.sync.aligned.m16n8k16.row.col.f32.f16.f16.f32 "
        "{%0,%1,%2,%3},{%4,%5,%6,%7},{%8,%9},{%0,%1,%2,%3};"
        : "+f"(d[0]), "+f"(d[1]), "+f"(d[2]), "+f"(d[3])
        : "r"(a[0]), "r"(a[1]), "r"(a[2]), "r"(a[3]), "r"(b[0]), "r"(b[1]));
}

// SMEM per CTA: [0,1024): BN luts; stages: 3 x (A 16KB | B 16KB), K-chunk 64.
#define OFF_ST 1024u
#define NSTAGE 3
#define STG_SZ 32768u
#define SMEM_REQ (512u + OFF_ST + (uint32_t)NSTAGE * STG_SZ)

// ============================ fused conversion kernel =======================
__global__ void conv_fused_kernel(const float* __restrict__ X,
                                  const float* __restrict__ w1,
                                  const float* __restrict__ w2,
                                  const float* __restrict__ w3) {
    const int bid = blockIdx.x, tid = threadIdx.x;
    if (bid < 25600) {
        __shared__ float t[64][33];
        const int b = bid / 400, rem = bid - b * 400;
        const int c0 = (rem & 15) * 64, hw0 = (rem >> 4) * 32;
        const int tx = tid & 31, ty = tid >> 5;
        #pragma unroll
        for (int i = 0; i < 8; i++) {
            int c = ty + i * 8, hw = hw0 + tx;
            t[c][tx] = (hw < HW) ? X[((size_t)b * 1024 + c0 + c) * HW + hw] : 0.f;
        }
        __syncthreads();
        #pragma unroll
        for (int i = 0; i < 4; i++) {
            int nl = ty + i * 8, hw = hw0 + nl;
            if (hw < HW) {
                size_t n = (size_t)b * HW + hw;
                __half2 h2 = __floats2half2_rn(t[2 * tx][nl], t[2 * tx + 1][nl]);
                ((__half2*)(g_x + n * 1024 + c0))[tx] = h2;
            }
        }
    } else {
        const int idx = (bid - 25600) * 256 + tid;
        if (idx < 256 * 1024)
            g_w1[idx] = __float2half_rn(w1[idx]);
        if (idx < 256 * 256 * 9) {
            int co = idx / 2304, rem = idx % 2304;
            int ci = rem / 9, tap = rem % 9;
            g_w2[co * 2304 + tap * 256 + ci] = __float2half_rn(w2[idx]);
        }
        if (idx < 1024 * 256)
            g_w3[idx] = __float2half_rn(w3[idx]);
    }
}

// ============================ HMMA GEMM =====================================
// Modes 1/2: CTA 128co x 112n (grid 896 = 3.03 waves). Mode 3: 128co x 128n.
// 128 threads (4 warps: 2m x 2n), warp tile 64 x (56|64), K-chunk 64, 3 stages,
// 2 CTAs/SM.
template <int MODE>
__global__ __launch_bounds__(128, 2)
void mma_gemm(const float* __restrict__ G, const float* __restrict__ Be,
              const float* __restrict__ Mu, const float* __restrict__ Va,
              const float* __restrict__ Xres, float* __restrict__ OUT)
{
    constexpr int KTOT = (MODE == 1) ? 1024 : (MODE == 2 ? 2304 : 256);
    constexpr int NC = KTOT / 64;
    constexpr int BN = (MODE == 3) ? 128 : 112;   // CTA n-tile
    constexpr int WN = BN / 2;                    // warp n-tile (64 or 56)
    constexpr int NU = WN / 8;                    // n8-tiles per warp (8 or 7)
    constexpr int NBL = BN / 16;                  // B-loader iters (8 or 7)

    extern __shared__ char smraw[];
    const uint32_t sbr = smem_u32(smraw);
    const uint32_t sb = (sbr + 511u) & ~511u;
    char* sm = smraw + (sb - sbr);

    const int tid = threadIdx.x, lane = tid & 31, wid = tid >> 5;
    const int wm = wid >> 1, wn = wid & 1;          // 2 x 2 warp grid
    const int n0 = blockIdx.x * BN;
    const int co0 = blockIdx.y * 128;

    float* scl = (float*)sm;
    float* shl = scl + 128;
    {
        int co = co0 + tid;
        float sc = G[co] * rsqrtf(Va[co] + EPS);
        scl[tid] = sc;
        shl[tid] = Be[co] - Mu[co] * sc;
    }

    const uint32_t stb = sb + OFF_ST;

    // ---- MODE 2: hoist per-thread B-row geometry out of the k-loop ----
    // row = (i*128+tid)>>3, seg = (i*128+tid)&7 are loop-invariant per i.
    size_t m2_rowbase[NBL];   // (n0+row)*256 + seg*8
    int    m2_h[NBL], m2_w[NBL];
    if (MODE == 2) {
        #pragma unroll
        for (int i = 0; i < NBL; i++) {
            int idx = i * 128 + tid, row = idx >> 3, seg = idx & 7;
            int n = n0 + row;
            int hw = n % HW;
            m2_h[i] = hw / 28;
            m2_w[i] = hw - (hw / 28) * 28;
            m2_rowbase[i] = (size_t)n * 256 + seg * 8;
        }
    }

    // ---- async chunk loader: stage = c % 3 holds k-window [c*64, +64) ----
    auto load_chunk = [&](int c) {
        const uint32_t st = stb + (uint32_t)(c % NSTAGE) * STG_SZ;
        const int k0 = c * 64;
        // A tile (weights): 128 co-rows x 128B
        #pragma unroll
        for (int i = 0; i < 8; i++) {
            int idx = i * 128 + tid, row = idx >> 3, seg = idx & 7;
            uint32_t so = st + (uint32_t)row * 128u +
                          (uint32_t)((seg * 16) ^ ((row & 7) * 16));
            const __half* gp;
            if (MODE == 1)      gp = g_w1 + (size_t)(co0 + row) * 1024 + k0 + seg * 8;
            else if (MODE == 2) gp = g_w2 + (size_t)(co0 + row) * 2304 + k0 + seg * 8;
            else                gp = g_w3 + (size_t)(co0 + row) * 256 + k0 + seg * 8;
            cp16(so, gp, 16);
        }
        // B tile (activations): BN n-rows x 128B at st+16KB
        if (MODE == 2) {
            // scalar per-chunk tap math; per-row work is just bounds + add
            const int tap = k0 >> 8, ci = k0 & 255;
            const int dh = tap / 3 - 1, dw = tap - (tap / 3) * 3 - 1;
            const long doff = (long)(dh * 28 + dw) * 256 + ci;
            #pragma unroll
            for (int i = 0; i < NBL; i++) {
                int idx = i * 128 + tid, row = idx >> 3, seg = idx & 7;
                uint32_t so = st + 16384u + (uint32_t)row * 128u +
                              (uint32_t)((seg * 16) ^ ((row & 7) * 16));
                const bool ok = ((unsigned)(m2_h[i] + dh) < 28u) &&
                                ((unsigned)(m2_w[i] + dw) < 28u);
                const __half* gp = g_o1 + (ok ? (size_t)((long)m2_rowbase[i] + doff)
                                              : (size_t)0);
                cp16(so, gp, ok ? 16u : 0u);
            }
        } else {
            #pragma unroll
            for (int i = 0; i < NBL; i++) {
                int idx = i * 128 + tid, row = idx >> 3, seg = idx & 7;
                uint32_t so = st + 16384u + (uint32_t)row * 128u +
                              (uint32_t)((seg * 16) ^ ((row & 7) * 16));
                if (MODE == 1)
                    cp16(so, g_x + (size_t)(n0 + row) * 1024 + k0 + seg * 8, 16);
                else
                    cp16(so, g_o2 + (size_t)(n0 + row) * 256 + k0 + seg * 8, 16);
            }
        }
    };

    // ---- prologue: 2 stages in flight ----
    load_chunk(0); CP_COMMIT();
    load_chunk(1); CP_COMMIT();

    float acc[4][NU][4];
    #pragma unroll
    for (int t = 0; t < 4; t++)
        #pragma unroll
        for (int u = 0; u < NU; u++)
            #pragma unroll
            for (int e = 0; e < 4; e++) acc[t][u][e] = 0.f;

    for (int c = 0; c < NC; c++) {
        CP_WAIT(1);
        __syncthreads();
        if (c + 2 < NC) load_chunk(c + 2);
        CP_COMMIT();            // unconditional: empty tail groups keep CP_WAIT(1) safe

        const uint32_t st = stb + (uint32_t)(c % NSTAGE) * STG_SZ;

        #pragma unroll
        for (int kk = 0; kk < 4; kk++) {
            uint32_t afr[4][4], bfr[NU / 2][4], btl[2];
            #pragma unroll
            for (int t = 0; t < 4; t++) {
                int row = wm * 64 + t * 16 + (lane & 7) + ((lane >> 3) & 1) * 8;
                int woff = kk * 32 + ((lane >> 4) & 1) * 16;
                ldm4(st + (uint32_t)row * 128u + (uint32_t)(woff ^ ((row & 7) * 16)), afr[t]);
            }
            #pragma unroll
            for (int t2 = 0; t2 < NU / 2; t2++) {
                int row = wn * WN + t2 * 16 + (lane & 7) + ((lane >> 4) & 1) * 8;
                int woff = kk * 32 + ((lane >> 3) & 1) * 16;
                ldm4(st + 16384u + (uint32_t)row * 128u + (uint32_t)(woff ^ ((row & 7) * 16)), bfr[t2]);
            }
            if (NU & 1) {   // odd tail n8-tile via ldmatrix.x2
                int row = wn * WN + (NU / 2) * 16 + (lane & 7);
                int woff = kk * 32 + ((lane >> 3) & 1) * 16;
                ldm2(st + 16384u + (uint32_t)row * 128u + (uint32_t)(woff ^ ((row & 7) * 16)), btl);
            }
            #pragma unroll
            for (int t = 0; t < 4; t++) {
                #pragma unroll
                for (int u = 0; u < (NU & ~1); u++)
                    mma16816(acc[t][u], afr[t], &bfr[u >> 1][(u & 1) * 2]);
                if (NU & 1)
                    mma16816(acc[t][NU - 1], afr[t], btl);
            }
        }
    }
    __syncthreads();

    // ---- epilogue ----
    const int r = lane >> 2, cb = (lane & 3) * 2;
    if (MODE == 3) {
        // BN in regs -> smem transpose [128 co][132-pitch n] fp32 ->
        // warp-per-row coalesced residual+relu+store, MLP=16 batches
        float* sE = (float*)(sm + OFF_ST);
        #pragma unroll
        for (int t = 0; t < 4; t++)
            #pragma unroll
            for (int u = 0; u < NU; u++)
                #pragma unroll
                for (int half = 0; half < 2; half++) {
                    const int col = wm * 64 + t * 16 + r + half * 8;
                    const float sc = scl[col], sh = shl[col];
                    const int nl = wn * WN + u * 8 + cb;
                    float* dst = sE + (size_t)col * 132 + nl;
                    dst[0] = fmaf(acc[t][u][half * 2 + 0], sc, sh);
                    dst[1] = fmaf(acc[t][u][half * 2 + 1], sc, sh);
                }
        __syncthreads();
        const int n = n0 + lane * 4;
        const int b = n / HW, hw = n - b * HW;       // float4 never crosses batch
        const size_t base = (size_t)b * (1024 * HW) + (size_t)(co0 + wid * 32) * HW + hw;
        #pragma unroll 1
        for (int g = 0; g < 2; g++) {
            float4 xv[16];
            #pragma unroll
            for (int i = 0; i < 16; i++)
                xv[i] = *(const float4*)(Xres + base + (size_t)(g * 16 + i) * HW);
            #pragma unroll
            for (int i = 0; i < 16; i++) {
                const int row = wid * 32 + g * 16 + i;
                float4 v = *(const float4*)(sE + (size_t)row * 132 + lane * 4);
                float4 o;
                o.x = fmaxf(v.x + xv[i].x, 0.f);
                o.y = fmaxf(v.y + xv[i].y, 0.f);
                o.z = fmaxf(v.z + xv[i].z, 0.f);
                o.w = fmaxf(v.w + xv[i].w, 0.f);
                *(float4*)(OUT + base + (size_t)(g * 16 + i) * HW) = o;
            }
        }
    } else {
        __half* sT = (__half*)(sm + OFF_ST);   // [BN n][136-pitch co] fp16
        #pragma unroll
        for (int t = 0; t < 4; t++)
            #pragma unroll
            for (int u = 0; u < NU; u++)
                #pragma unroll
                for (int half = 0; half < 2; half++) {
                    const int col = wm * 64 + t * 16 + r + half * 8;
                    const float sc = scl[col], sh = shl[col];
                    #pragma unroll
                    for (int e = 0; e < 2; e++) {
                        const int nl = wn * WN + u * 8 + cb + e;
                        float v = fmaxf(fmaf(acc[t][u][half * 2 + e], sc, sh), 0.f);
                        sT[nl * 136 + col] = __float2half_rn(v);
                    }
                }
        __syncthreads();
        if (tid < BN) {
            const uint4* srow = (const uint4*)(sT + tid * 136);
            uint4* drow = (uint4*)(((MODE == 1) ? g_o1 : g_o2) +
                                   (size_t)(n0 + tid) * 256 + co0);
            #pragma unroll
            for (int q = 0; q < 16; q++) drow[q] = srow[q];
        }
    }
}

// ============================ launcher ======================================
extern "C" void kernel_launch(void* const* d_in, const int* in_sizes, int n_in,
                              void* d_out, int out_size)
{
    const float* x  = (const float*)d_in[0];
    const float* w1 = (const float*)d_in[1];
    const float* w2 = (const float*)d_in[2];
    const float* w3 = (const float*)d_in[3];
    const float* g1 = (const float*)d_in[4];
    const float* b1 = (const float*)d_in[5];
    const float* m1 = (const float*)d_in[6];
    const float* v1 = (const float*)d_in[7];
    const float* g2 = (const float*)d_in[8];
    const float* b2 = (const float*)d_in[9];
    const float* m2 = (const float*)d_in[10];
    const float* v2 = (const float*)d_in[11];
    const float* g3 = (const float*)d_in[12];
    const float* b3 = (const float*)d_in[13];
    const float* m3 = (const float*)d_in[14];
    const float* v3 = (const float*)d_in[15];
    float* out = (float*)d_out;

    cudaFuncSetAttribute(mma_gemm<1>, cudaFuncAttributeMaxDynamicSharedMemorySize, SMEM_REQ);
    cudaFuncSetAttribute(mma_gemm<2>, cudaFuncAttributeMaxDynamicSharedMemorySize, SMEM_REQ);
    cudaFuncSetAttribute(mma_gemm<3>, cudaFuncAttributeMaxDynamicSharedMemorySize, SMEM_REQ);

    conv_fused_kernel<<<27904, 256>>>(x, w1, w2, w3);

    mma_gemm<1><<<dim3(448, 2), 128, SMEM_REQ>>>(g1, b1, m1, v1, nullptr, nullptr);
    mma_gemm<2><<<dim3(448, 2), 128, SMEM_REQ>>>(g2, b2, m2, v2, nullptr, nullptr);
    mma_gemm<3><<<dim3(392, 8), 128, SMEM_REQ>>>(g3, b3, m3, v3, x, out);
}

// round 17
// speedup vs baseline: 1.0105x; 1.0105x over previous
#include <cuda_runtime.h>
#include <cuda_fp16.h>
#include <cstdint>

#define EPS 1e-5f
#define HW 784
#define NTOT 50176

// ============================ device scratch ================================
__device__ __align__(1024) __half g_x[(size_t)NTOT * 1024];  // X:  [n][1024]
__device__ __align__(1024) __half g_o1[(size_t)NTOT * 256];  // o1: [n][256]
__device__ __align__(1024) __half g_o2[(size_t)NTOT * 256];  // o2: [n][256]
__device__ __align__(1024) __half g_w1[256 * 1024];          // [co][1024]
__device__ __align__(1024) __half g_w2[256 * 2304];          // [co][2304], k=tap*256+ci
__device__ __align__(1024) __half g_w3[1024 * 256];          // [co][256]

// ============================ PTX helpers ===================================
__device__ __forceinline__ uint32_t smem_u32(const void* p) {
    uint32_t a;
    asm("{ .reg .u64 t; cvta.to.shared.u64 t, %1; cvt.u32.u64 %0, t; }" : "=r"(a) : "l"(p));
    return a;
}
__device__ __forceinline__ void cp16(uint32_t s, const void* g, uint32_t sz) {
    asm volatile("cp.async.cg.shared.global [%0], [%1], 16, %2;"
                 :: "r"(s), "l"(g), "r"(sz));
}
#define CP_COMMIT() asm volatile("cp.async.commit_group;" ::: "memory")
#define CP_WAIT(N)  asm volatile("cp.async.wait_group %0;" :: "n"(N) : "memory")

__device__ __forceinline__ void ldm4(uint32_t a, uint32_t r[4]) {
    asm volatile("ldmatrix.sync.aligned.m8n8.x4.shared.b16 {%0,%1,%2,%3}, [%4];"
                 : "=r"(r[0]), "=r"(r[1]), "=r"(r[2]), "=r"(r[3]) : "r"(a));
}
__device__ __forceinline__ void ldm2(uint32_t a, uint32_t r[2]) {
    asm volatile("ldmatrix.sync.aligned.m8n8.x2.shared.b16 {%0,%1}, [%2];"
                 : "=r"(r[0]), "=r"(r[1]) : "r"(a));
}
__device__ __forceinline__ void mma16816(float d[4], const uint32_t a[4], const uint32_t b[2]) {
    asm("mma.sync.aligned.m16n8k16.row.col.f32.f16.f16.f32 "
        "{%0,%1,%2,%3},{%4,%5,%6,%7},{%8,%9},{%0,%1,%2,%3};"
        : "+f"(d[0]), "+f"(d[1]), "+f"(d[2]), "+f"(d[3])
        : "r"(a[0]), "r"(a[1]), "r"(a[2]), "r"(a[3]), "r"(b[0]), "r"(b[1]));
}

// SMEM per CTA: [0,1024): BN luts; stages: 3 x (A 16KB | B 16KB), K-chunk 64.
#define OFF_ST 1024u
#define NSTAGE 3
#define STG_SZ 32768u
#define SMEM_REQ (512u + OFF_ST + (uint32_t)NSTAGE * STG_SZ)

// ============================ fused conversion kernel =======================
__global__ void conv_fused_kernel(const float* __restrict__ X,
                                  const float* __restrict__ w1,
                                  const float* __restrict__ w2,
                                  const float* __restrict__ w3) {
    const int bid = blockIdx.x, tid = threadIdx.x;
    if (bid < 25600) {
        __shared__ float t[64][33];
        const int b = bid / 400, rem = bid - b * 400;
        const int c0 = (rem & 15) * 64, hw0 = (rem >> 4) * 32;
        const int tx = tid & 31, ty = tid >> 5;
        #pragma unroll
        for (int i = 0; i < 8; i++) {
            int c = ty + i * 8, hw = hw0 + tx;
            t[c][tx] = (hw < HW) ? X[((size_t)b * 1024 + c0 + c) * HW + hw] : 0.f;
        }
        __syncthreads();
        #pragma unroll
        for (int i = 0; i < 4; i++) {
            int nl = ty + i * 8, hw = hw0 + nl;
            if (hw < HW) {
                size_t n = (size_t)b * HW + hw;
                __half2 h2 = __floats2half2_rn(t[2 * tx][nl], t[2 * tx + 1][nl]);
                ((__half2*)(g_x + n * 1024 + c0))[tx] = h2;
            }
        }
    } else {
        const int idx = (bid - 25600) * 256 + tid;
        if (idx < 256 * 1024)
            g_w1[idx] = __float2half_rn(w1[idx]);
        if (idx < 256 * 256 * 9) {
            int co = idx / 2304, rem = idx % 2304;
            int ci = rem / 9, tap = rem % 9;
            g_w2[co * 2304 + tap * 256 + ci] = __float2half_rn(w2[idx]);
        }
        if (idx < 1024 * 256)
            g_w3[idx] = __float2half_rn(w3[idx]);
    }
}

// ============================ HMMA GEMM =====================================
// Grid mapping: co = blockIdx.x (FASTEST-varying) so all co-splits of one
// n-tile are adjacent in the wave and share their B tile in L2.
// Modes 1/2: grid (2, 448), CTA 128co x 112n. Mode 3: grid (8, 392), 128x128.
// 128 threads (4 warps: 2m x 2n), warp tile 64 x (56|64), K-chunk 64, 3 stages,
// 2 CTAs/SM.
template <int MODE>
__global__ __launch_bounds__(128, 2)
void mma_gemm(const float* __restrict__ G, const float* __restrict__ Be,
              const float* __restrict__ Mu, const float* __restrict__ Va,
              const float* __restrict__ Xres, float* __restrict__ OUT)
{
    constexpr int KTOT = (MODE == 1) ? 1024 : (MODE == 2 ? 2304 : 256);
    constexpr int NC = KTOT / 64;
    constexpr int BN = (MODE == 3) ? 128 : 112;   // CTA n-tile
    constexpr int WN = BN / 2;                    // warp n-tile (64 or 56)
    constexpr int NU = WN / 8;                    // n8-tiles per warp (8 or 7)

    extern __shared__ char smraw[];
    const uint32_t sbr = smem_u32(smraw);
    const uint32_t sb = (sbr + 511u) & ~511u;
    char* sm = smraw + (sb - sbr);

    const int tid = threadIdx.x, lane = tid & 31, wid = tid >> 5;
    const int wm = wid >> 1, wn = wid & 1;          // 2 x 2 warp grid
    const int n0 = blockIdx.y * BN;                 // n tile (slow axis)
    const int co0 = blockIdx.x * 128;               // co tile (fast axis -> L2 reuse)

    float* scl = (float*)sm;
    float* shl = scl + 128;
    {
        int co = co0 + tid;
        float sc = G[co] * rsqrtf(Va[co] + EPS);
        scl[tid] = sc;
        shl[tid] = Be[co] - Mu[co] * sc;
    }

    const uint32_t stb = sb + OFF_ST;

    // ---- async chunk loader: stage = c % 3 holds k-window [c*64, +64) ----
    auto load_chunk = [&](int c) {
        const uint32_t st = stb + (uint32_t)(c % NSTAGE) * STG_SZ;
        const int k0 = c * 64;
        // A tile (weights): 128 co-rows x 128B
        #pragma unroll
        for (int i = 0; i < 8; i++) {
            int idx = i * 128 + tid, row = idx >> 3, seg = idx & 7;
            uint32_t so = st + (uint32_t)row * 128u +
                          (uint32_t)((seg * 16) ^ ((row & 7) * 16));
            const __half* gp;
            if (MODE == 1)      gp = g_w1 + (size_t)(co0 + row) * 1024 + k0 + seg * 8;
            else if (MODE == 2) gp = g_w2 + (size_t)(co0 + row) * 2304 + k0 + seg * 8;
            else                gp = g_w3 + (size_t)(co0 + row) * 256 + k0 + seg * 8;
            cp16(so, gp, 16);
        }
        // B tile (activations): BN n-rows x 128B at st+16KB
        #pragma unroll
        for (int i = 0; i < BN / 16; i++) {
            int idx = i * 128 + tid, row = idx >> 3, seg = idx & 7;
            uint32_t so = st + 16384u + (uint32_t)row * 128u +
                          (uint32_t)((seg * 16) ^ ((row & 7) * 16));
            if (MODE == 1) {
                cp16(so, g_x + (size_t)(n0 + row) * 1024 + k0 + seg * 8, 16);
            } else if (MODE == 3) {
                cp16(so, g_o2 + (size_t)(n0 + row) * 256 + k0 + seg * 8, 16);
            } else {
                const int kk0 = k0 + seg * 8;
                const int tap = kk0 >> 8, ci = kk0 & 255;
                const int dh = tap / 3 - 1, dw = tap % 3 - 1;
                const int n = n0 + row;
                const int hw = n % HW, h = hw / 28, w = hw % 28;
                const bool ok = ((unsigned)(h + dh) < 28u) && ((unsigned)(w + dw) < 28u);
                const __half* gp = g_o1 + (ok ?
                    ((size_t)(n + dh * 28 + dw) * 256 + ci) : (size_t)0);
                cp16(so, gp, ok ? 16u : 0u);
            }
        }
    };

    // ---- prologue: 2 stages in flight ----
    load_chunk(0); CP_COMMIT();
    load_chunk(1); CP_COMMIT();

    float acc[4][NU][4];
    #pragma unroll
    for (int t = 0; t < 4; t++)
        #pragma unroll
        for (int u = 0; u < NU; u++)
            #pragma unroll
            for (int e = 0; e < 4; e++) acc[t][u][e] = 0.f;

    for (int c = 0; c < NC; c++) {
        CP_WAIT(1);
        __syncthreads();
        if (c + 2 < NC) load_chunk(c + 2);
        CP_COMMIT();            // unconditional: empty tail groups keep CP_WAIT(1) safe

        const uint32_t st = stb + (uint32_t)(c % NSTAGE) * STG_SZ;

        #pragma unroll
        for (int kk = 0; kk < 4; kk++) {
            uint32_t afr[4][4], bfr[NU / 2][4], btl[2];
            #pragma unroll
            for (int t = 0; t < 4; t++) {
                int row = wm * 64 + t * 16 + (lane & 7) + ((lane >> 3) & 1) * 8;
                int woff = kk * 32 + ((lane >> 4) & 1) * 16;
                ldm4(st + (uint32_t)row * 128u + (uint32_t)(woff ^ ((row & 7) * 16)), afr[t]);
            }
            #pragma unroll
            for (int t2 = 0; t2 < NU / 2; t2++) {
                int row = wn * WN + t2 * 16 + (lane & 7) + ((lane >> 4) & 1) * 8;
                int woff = kk * 32 + ((lane >> 3) & 1) * 16;
                ldm4(st + 16384u + (uint32_t)row * 128u + (uint32_t)(woff ^ ((row & 7) * 16)), bfr[t2]);
            }
            if (NU & 1) {   // odd tail n8-tile via ldmatrix.x2
                int row = wn * WN + (NU / 2) * 16 + (lane & 7);
                int woff = kk * 32 + ((lane >> 3) & 1) * 16;
                ldm2(st + 16384u + (uint32_t)row * 128u + (uint32_t)(woff ^ ((row & 7) * 16)), btl);
            }
            #pragma unroll
            for (int t = 0; t < 4; t++) {
                #pragma unroll
                for (int u = 0; u < (NU & ~1); u++)
                    mma16816(acc[t][u], afr[t], &bfr[u >> 1][(u & 1) * 2]);
                if (NU & 1)
                    mma16816(acc[t][NU - 1], afr[t], btl);
            }
        }
    }
    __syncthreads();

    // ---- epilogue ----
    const int r = lane >> 2, cb = (lane & 3) * 2;
    if (MODE == 3) {
        // BN in regs -> smem transpose [128 co][132-pitch n] fp32 ->
        // warp-per-row coalesced residual+relu+store, MLP=8 batches
        float* sE = (float*)(sm + OFF_ST);
        #pragma unroll
        for (int t = 0; t < 4; t++)
            #pragma unroll
            for (int u = 0; u < NU; u++)
                #pragma unroll
                for (int half = 0; half < 2; half++) {
                    const int col = wm * 64 + t * 16 + r + half * 8;
                    const float sc = scl[col], sh = shl[col];
                    const int nl = wn * WN + u * 8 + cb;
                    float* dst = sE + (size_t)col * 132 + nl;
                    dst[0] = fmaf(acc[t][u][half * 2 + 0], sc, sh);
                    dst[1] = fmaf(acc[t][u][half * 2 + 1], sc, sh);
                }
        __syncthreads();
        const int n = n0 + lane * 4;
        const int b = n / HW, hw = n - b * HW;       // float4 never crosses batch
        const size_t base = (size_t)b * (1024 * HW) + (size_t)(co0 + wid * 32) * HW + hw;
        #pragma unroll 1
        for (int g = 0; g < 4; g++) {
            float4 v[8], xv[8];
            #pragma unroll
            for (int i = 0; i < 8; i++) {
                const int row = wid * 32 + g * 8 + i;
                v[i]  = *(const float4*)(sE + (size_t)row * 132 + lane * 4);
                xv[i] = *(const float4*)(Xres + base + (size_t)(g * 8 + i) * HW);
            }
            #pragma unroll
            for (int i = 0; i < 8; i++) {
                float4 o;
                o.x = fmaxf(v[i].x + xv[i].x, 0.f);
                o.y = fmaxf(v[i].y + xv[i].y, 0.f);
                o.z = fmaxf(v[i].z + xv[i].z, 0.f);
                o.w = fmaxf(v[i].w + xv[i].w, 0.f);
                *(float4*)(OUT + base + (size_t)(g * 8 + i) * HW) = o;
            }
        }
    } else {
        __half* sT = (__half*)(sm + OFF_ST);   // [BN n][136-pitch co] fp16
        #pragma unroll
        for (int t = 0; t < 4; t++)
            #pragma unroll
            for (int u = 0; u < NU; u++)
                #pragma unroll
                for (int half = 0; half < 2; half++) {
                    const int col = wm * 64 + t * 16 + r + half * 8;
                    const float sc = scl[col], sh = shl[col];
                    #pragma unroll
                    for (int e = 0; e < 2; e++) {
                        const int nl = wn * WN + u * 8 + cb + e;
                        float v = fmaxf(fmaf(acc[t][u][half * 2 + e], sc, sh), 0.f);
                        sT[nl * 136 + col] = __float2half_rn(v);
                    }
                }
        __syncthreads();
        if (tid < BN) {
            const uint4* srow = (const uint4*)(sT + tid * 136);
            uint4* drow = (uint4*)(((MODE == 1) ? g_o1 : g_o2) +
                                   (size_t)(n0 + tid) * 256 + co0);
            #pragma unroll
            for (int q = 0; q < 16; q++) drow[q] = srow[q];
        }
    }
}

// ============================ launcher ======================================
extern "C" void kernel_launch(void* const* d_in, const int* in_sizes, int n_in,
                              void* d_out, int out_size)
{
    const float* x  = (const float*)d_in[0];
    const float* w1 = (const float*)d_in[1];
    const float* w2 = (const float*)d_in[2];
    const float* w3 = (const float*)d_in[3];
    const float* g1 = (const float*)d_in[4];
    const float* b1 = (const float*)d_in[5];
    const float* m1 = (const float*)d_in[6];
    const float* v1 = (const float*)d_in[7];
    const float* g2 = (const float*)d_in[8];
    const float* b2 = (const float*)d_in[9];
    const float* m2 = (const float*)d_in[10];
    const float* v2 = (const float*)d_in[11];
    const float* g3 = (const float*)d_in[12];
    const float* b3 = (const float*)d_in[13];
    const float* m3 = (const float*)d_in[14];
    const float* v3 = (const float*)d_in[15];
    float* out = (float*)d_out;

    cudaFuncSetAttribute(mma_gemm<1>, cudaFuncAttributeMaxDynamicSharedMemorySize, SMEM_REQ);
    cudaFuncSetAttribute(mma_gemm<2>, cudaFuncAttributeMaxDynamicSharedMemorySize, SMEM_REQ);
    cudaFuncSetAttribute(mma_gemm<3>, cudaFuncAttributeMaxDynamicSharedMemorySize, SMEM_REQ);

    conv_fused_kernel<<<27904, 256>>>(x, w1, w2, w3);

    // co on blockIdx.x (fast axis) -> co-splits of one n-tile adjacent in wave
    mma_gemm<1><<<dim3(2, 448), 128, SMEM_REQ>>>(g1, b1, m1, v1, nullptr, nullptr);
    mma_gemm<2><<<dim3(2, 448), 128, SMEM_REQ>>>(g2, b2, m2, v2, nullptr, nullptr);
    mma_gemm<3><<<dim3(8, 392), 128, SMEM_REQ>>>(g3, b3, m3, v3, x, out);
}